// round 2
// baseline (speedup 1.0000x reference)
#include <cuda_runtime.h>
#include <cstdint>

// Flash attention, tf32 mma.sync, round 2: 4 warps x m32 warp-tiles.
// B-fragments (K and V) loaded once per (n,k) pair and reused across the two
// m-fragments in registers -> smem read bytes cut ~1.6x vs round 1.

namespace {

constexpr int SEQ = 2048;
constexpr int HD = 64;
constexpr int BM = 128;          // q rows per CTA
constexpr int BN = 64;           // kv rows per iteration
constexpr int THREADS = 128;     // 4 warps, 32 q rows each
constexpr int NKV = SEQ / BN;    // 32

constexpr int QP_STRIDE = 68;
constexpr int K_STRIDE  = 68;
constexpr int V_STRIDE  = 72;

constexpr int SK_OFF = BM * QP_STRIDE;               // 8704
constexpr int SV_OFF = SK_OFF + BN * K_STRIDE;       // 13056
constexpr int SMEM_FLOATS = SV_OFF + BN * V_STRIDE;  // 17664 -> 70656 B

__device__ __forceinline__ uint32_t f2tf(float x) {
    uint32_t r;
    asm("cvt.rna.tf32.f32 %0, %1;" : "=r"(r) : "f"(x));
    return r;
}

__device__ __forceinline__ void mma_tf32(float c[4], const uint32_t a[4], const uint32_t b[2]) {
    asm volatile(
        "mma.sync.aligned.m16n8k8.row.col.f32.tf32.tf32.f32 "
        "{%0,%1,%2,%3}, {%4,%5,%6,%7}, {%8,%9}, {%0,%1,%2,%3};\n"
        : "+f"(c[0]), "+f"(c[1]), "+f"(c[2]), "+f"(c[3])
        : "r"(a[0]), "r"(a[1]), "r"(a[2]), "r"(a[3]), "r"(b[0]), "r"(b[1]));
}

__global__ void __launch_bounds__(THREADS)
fa_tf32_kernel(const float* __restrict__ q, const float* __restrict__ k,
               const float* __restrict__ v, float* __restrict__ out)
{
    extern __shared__ float smem[];
    float* sQ = smem;            // [BM][QP_STRIDE]  (reused as P tile)
    float* sK = smem + SK_OFF;   // [BN][K_STRIDE]
    float* sV = smem + SV_OFF;   // [BN][V_STRIDE]

    const int bh   = blockIdx.y;
    const int qt   = blockIdx.x;
    const int tid  = threadIdx.x;
    const int wid  = tid >> 5;
    const int lane = tid & 31;
    const int g    = lane >> 2;   // 0..7
    const int t    = lane & 3;    // 0..3

    const float scale = 0.125f;
    const int base = bh * SEQ * HD;

    // ---- load Q tile (scaled, tf32-rounded) ----
    {
        const float* qg = q + base + qt * BM * HD;
        int r0 = tid >> 4;            // 0..7
        int c  = (tid & 15) * 4;
        #pragma unroll
        for (int i = 0; i < 16; i++) {
            int r = r0 + i * 8;
            float4 val = *reinterpret_cast<const float4*>(qg + r * HD + c);
            uint4 o;
            o.x = f2tf(val.x * scale); o.y = f2tf(val.y * scale);
            o.z = f2tf(val.z * scale); o.w = f2tf(val.w * scale);
            *reinterpret_cast<uint4*>(&sQ[r * QP_STRIDE + c]) = o;
        }
    }
    __syncthreads();

    // ---- hoist Q fragments: 2 m-frags x 8 k-tiles x 4 regs ----
    const int m0 = wid * 32;
    uint32_t qf[2][8][4];
    #pragma unroll
    for (int mf = 0; mf < 2; mf++) {
        #pragma unroll
        for (int kt = 0; kt < 8; kt++) {
            const float* p = &sQ[(m0 + mf * 16 + g) * QP_STRIDE + kt * 8 + t];
            qf[mf][kt][0] = __float_as_uint(p[0]);
            qf[mf][kt][1] = __float_as_uint(p[8 * QP_STRIDE]);
            qf[mf][kt][2] = __float_as_uint(p[4]);
            qf[mf][kt][3] = __float_as_uint(p[8 * QP_STRIDE + 4]);
        }
    }

    float oacc[2][8][4];
    #pragma unroll
    for (int mf = 0; mf < 2; mf++)
        #pragma unroll
        for (int i = 0; i < 8; i++)
            #pragma unroll
            for (int j = 0; j < 4; j++) oacc[mf][i][j] = 0.f;

    float mrow[2][2] = {{-1e30f, -1e30f}, {-1e30f, -1e30f}};
    float lrow[2][2] = {{0.f, 0.f}, {0.f, 0.f}};

    for (int kvt = 0; kvt < NKV; kvt++) {
        __syncthreads();   // K/V fully consumed from previous iteration

        // ---- load K,V tiles (tf32-rounded) ----
        {
            const float* kg = k + base + kvt * BN * HD;
            const float* vg = v + base + kvt * BN * HD;
            int r0 = tid >> 4;
            int c  = (tid & 15) * 4;
            #pragma unroll
            for (int i = 0; i < 8; i++) {
                int r = r0 + i * 8;
                float4 kv4 = *reinterpret_cast<const float4*>(kg + r * HD + c);
                uint4 ok;
                ok.x = f2tf(kv4.x); ok.y = f2tf(kv4.y); ok.z = f2tf(kv4.z); ok.w = f2tf(kv4.w);
                *reinterpret_cast<uint4*>(&sK[r * K_STRIDE + c]) = ok;
                float4 vv4 = *reinterpret_cast<const float4*>(vg + r * HD + c);
                uint4 ov;
                ov.x = f2tf(vv4.x); ov.y = f2tf(vv4.y); ov.z = f2tf(vv4.z); ov.w = f2tf(vv4.w);
                *reinterpret_cast<uint4*>(&sV[r * V_STRIDE + c]) = ov;
            }
        }
        __syncthreads();

        // ---- S = (Q*scale) @ K^T : warp computes 32x64 ----
        float sacc[2][8][4];
        #pragma unroll
        for (int mf = 0; mf < 2; mf++)
            #pragma unroll
            for (int i = 0; i < 8; i++) {
                sacc[mf][i][0] = 0.f; sacc[mf][i][1] = 0.f;
                sacc[mf][i][2] = 0.f; sacc[mf][i][3] = 0.f;
            }
        #pragma unroll
        for (int nt = 0; nt < 8; nt++) {
            #pragma unroll
            for (int kt = 0; kt < 8; kt++) {
                uint32_t bf[2];
                const float* kp = &sK[(nt * 8 + g) * K_STRIDE + kt * 8 + t];
                bf[0] = __float_as_uint(kp[0]);
                bf[1] = __float_as_uint(kp[4]);
                mma_tf32(sacc[0][nt], qf[0][kt], bf);   // B-frag reused across m-frags
                mma_tf32(sacc[1][nt], qf[1][kt], bf);
            }
        }

        // ---- online softmax (per m-frag: rows g and g+8) ----
        #pragma unroll
        for (int mf = 0; mf < 2; mf++) {
            float tmax0 = -1e30f, tmax1 = -1e30f;
            #pragma unroll
            for (int nt = 0; nt < 8; nt++) {
                tmax0 = fmaxf(tmax0, fmaxf(sacc[mf][nt][0], sacc[mf][nt][1]));
                tmax1 = fmaxf(tmax1, fmaxf(sacc[mf][nt][2], sacc[mf][nt][3]));
            }
            tmax0 = fmaxf(tmax0, __shfl_xor_sync(0xffffffffu, tmax0, 1));
            tmax0 = fmaxf(tmax0, __shfl_xor_sync(0xffffffffu, tmax0, 2));
            tmax1 = fmaxf(tmax1, __shfl_xor_sync(0xffffffffu, tmax1, 1));
            tmax1 = fmaxf(tmax1, __shfl_xor_sync(0xffffffffu, tmax1, 2));

            float mn0 = fmaxf(mrow[mf][0], tmax0);
            float mn1 = fmaxf(mrow[mf][1], tmax1);
            float corr0 = __expf(mrow[mf][0] - mn0);
            float corr1 = __expf(mrow[mf][1] - mn1);
            mrow[mf][0] = mn0; mrow[mf][1] = mn1;

            float ts0 = 0.f, ts1 = 0.f;
            const int prow = (m0 + mf * 16 + g) * QP_STRIDE;
            #pragma unroll
            for (int nt = 0; nt < 8; nt++) {
                float p00 = __expf(sacc[mf][nt][0] - mn0);
                float p01 = __expf(sacc[mf][nt][1] - mn0);
                float p10 = __expf(sacc[mf][nt][2] - mn1);
                float p11 = __expf(sacc[mf][nt][3] - mn1);
                ts0 += p00 + p01;
                ts1 += p10 + p11;
                float2 lo = make_float2(__uint_as_float(f2tf(p00)), __uint_as_float(f2tf(p01)));
                float2 hi = make_float2(__uint_as_float(f2tf(p10)), __uint_as_float(f2tf(p11)));
                *reinterpret_cast<float2*>(&sQ[prow + nt * 8 + 2 * t]) = lo;
                *reinterpret_cast<float2*>(&sQ[prow + 8 * QP_STRIDE + nt * 8 + 2 * t]) = hi;
            }
            ts0 += __shfl_xor_sync(0xffffffffu, ts0, 1);
            ts0 += __shfl_xor_sync(0xffffffffu, ts0, 2);
            ts1 += __shfl_xor_sync(0xffffffffu, ts1, 1);
            ts1 += __shfl_xor_sync(0xffffffffu, ts1, 2);
            lrow[mf][0] = lrow[mf][0] * corr0 + ts0;
            lrow[mf][1] = lrow[mf][1] * corr1 + ts1;

            #pragma unroll
            for (int dt = 0; dt < 8; dt++) {
                oacc[mf][dt][0] *= corr0; oacc[mf][dt][1] *= corr0;
                oacc[mf][dt][2] *= corr1; oacc[mf][dt][3] *= corr1;
            }
        }

        __syncwarp();   // this warp's P rows visible across its lanes

        // ---- O += P @ V ----
        #pragma unroll
        for (int kt = 0; kt < 8; kt++) {
            uint32_t af[2][4];
            #pragma unroll
            for (int mf = 0; mf < 2; mf++) {
                const float* pp = &sQ[(m0 + mf * 16 + g) * QP_STRIDE + kt * 8 + t];
                af[mf][0] = __float_as_uint(pp[0]);
                af[mf][1] = __float_as_uint(pp[8 * QP_STRIDE]);
                af[mf][2] = __float_as_uint(pp[4]);
                af[mf][3] = __float_as_uint(pp[8 * QP_STRIDE + 4]);
            }
            #pragma unroll
            for (int dt = 0; dt < 8; dt++) {
                uint32_t bf[2];
                const float* vp = &sV[(kt * 8 + t) * V_STRIDE + dt * 8 + g];
                bf[0] = __float_as_uint(vp[0]);
                bf[1] = __float_as_uint(vp[4 * V_STRIDE]);
                mma_tf32(oacc[0][dt], af[0], bf);   // V-frag reused across m-frags
                mma_tf32(oacc[1][dt], af[1], bf);
            }
        }
    }

    // ---- epilogue: O /= l, store ----
    float* og = out + base + qt * BM * HD;
    #pragma unroll
    for (int mf = 0; mf < 2; mf++) {
        float inv0 = 1.f / lrow[mf][0];
        float inv1 = 1.f / lrow[mf][1];
        int r = m0 + mf * 16 + g;
        #pragma unroll
        for (int dt = 0; dt < 8; dt++) {
            int c = dt * 8 + 2 * t;
            float2 v0 = make_float2(oacc[mf][dt][0] * inv0, oacc[mf][dt][1] * inv0);
            float2 v1 = make_float2(oacc[mf][dt][2] * inv1, oacc[mf][dt][3] * inv1);
            *reinterpret_cast<float2*>(og + r * HD + c) = v0;
            *reinterpret_cast<float2*>(og + (r + 8) * HD + c) = v1;
        }
    }
}

}  // namespace

extern "C" void kernel_launch(void* const* d_in, const int* in_sizes, int n_in,
                              void* d_out, int out_size) {
    const float* q = (const float*)d_in[0];
    const float* k = (const float*)d_in[1];
    const float* v = (const float*)d_in[2];
    float* out = (float*)d_out;

    const size_t smem_bytes = SMEM_FLOATS * sizeof(float);
    cudaFuncSetAttribute(fa_tf32_kernel,
                         cudaFuncAttributeMaxDynamicSharedMemorySize, (int)smem_bytes);

    dim3 grid(SEQ / BM, 64);   // 16 q-tiles x (B*H = 64)
    fa_tf32_kernel<<<grid, THREADS, smem_bytes>>>(q, k, v, out);
}

// round 4
// speedup vs baseline: 2.3225x; 2.3225x over previous
#include <cuda_runtime.h>
#include <cuda_fp16.h>
#include <cstdint>

// Flash attention, fp16 mma.sync m16n8k16 (fp32 accum), round 4.
// B=4,H=16,S=2048,D=64. 8 warps x m16. fp16 smem tiles halve crossbar bytes
// and double MACs/instruction vs tf32 k8. V transposed to [d][kv] during load.

namespace {

constexpr int SEQ = 2048, HD = 64, BM = 128, BN = 64, THREADS = 256;
constexpr int NKV = SEQ / BN;

// fp16 tile rows of 64 elems = 128B, padded to 144B = 36 words.
// stride 36 ≡ 4 (mod 32) -> fragment LDS bank = 4g+t (+const): conflict-free.
constexpr int WSTR = 36;
constexpr int SK_OFF  = BM * WSTR;            // Q/P region: 128 rows
constexpr int SVT_OFF = SK_OFF + BN * WSTR;   // K region: 64 rows
constexpr int SMEM_WORDS = SVT_OFF + HD * WSTR;  // VT region: 64 rows -> 9216 w = 36864 B

__device__ __forceinline__ uint32_t f2h2(float lo, float hi) {
    uint32_t r;
    asm("cvt.rn.f16x2.f32 %0, %1, %2;" : "=r"(r) : "f"(hi), "f"(lo));  // d.lo=%2, d.hi=%1
    return r;
}

__device__ __forceinline__ void mma_f16(float c[4], const uint32_t a[4], const uint32_t b[2]) {
    asm volatile(
        "mma.sync.aligned.m16n8k16.row.col.f32.f16.f16.f32 "
        "{%0,%1,%2,%3}, {%4,%5,%6,%7}, {%8,%9}, {%0,%1,%2,%3};\n"
        : "+f"(c[0]), "+f"(c[1]), "+f"(c[2]), "+f"(c[3])
        : "r"(a[0]), "r"(a[1]), "r"(a[2]), "r"(a[3]), "r"(b[0]), "r"(b[1]));
}

__global__ void __launch_bounds__(THREADS, 2)
fa_f16_kernel(const float* __restrict__ q, const float* __restrict__ k,
              const float* __restrict__ v, float* __restrict__ out)
{
    extern __shared__ uint32_t smem[];
    uint32_t* sQ  = smem;             // [128][36w] fp16 Q, reused as P
    uint32_t* sK  = smem + SK_OFF;    // [64][36w]  fp16 K  [kv][d]
    uint32_t* sVT = smem + SVT_OFF;   // [64][36w]  fp16 V^T [d][kv]

    const int bh   = blockIdx.y;
    const int qt   = blockIdx.x;
    const int tid  = threadIdx.x;
    const int wid  = tid >> 5;
    const int lane = tid & 31;
    const int g    = lane >> 2;   // 0..7
    const int t    = lane & 3;    // 0..3
    const int base = bh * SEQ * HD;

    // ---- load Q (scaled, fp16) ----
    {
        const float* qg = q + base + qt * BM * HD;
        #pragma unroll
        for (int i = 0; i < 8; i++) {
            int fi = tid + i * THREADS;          // 2048 float4s
            int m = fi >> 4, c4 = fi & 15;
            float4 val = *reinterpret_cast<const float4*>(qg + m * HD + c4 * 4);
            uint2 o;
            o.x = f2h2(val.x * 0.125f, val.y * 0.125f);
            o.y = f2h2(val.z * 0.125f, val.w * 0.125f);
            *reinterpret_cast<uint2*>(&sQ[m * WSTR + c4 * 2]) = o;
        }
    }
    __syncthreads();

    // ---- hoist Q fragments: 4 k-steps (k16) x 4 regs ----
    const int m0 = wid * 16;
    uint32_t qf[4][4];
    #pragma unroll
    for (int kt = 0; kt < 4; kt++) {
        const uint32_t* p = &sQ[(m0 + g) * WSTR + kt * 8 + t];
        qf[kt][0] = p[0];
        qf[kt][1] = p[8 * WSTR];
        qf[kt][2] = p[4];
        qf[kt][3] = p[8 * WSTR + 4];
    }

    float oacc[8][4];
    #pragma unroll
    for (int i = 0; i < 8; i++)
        #pragma unroll
        for (int j = 0; j < 4; j++) oacc[i][j] = 0.f;

    float mrow0 = -1e30f, mrow1 = -1e30f;
    float lrow0 = 0.f, lrow1 = 0.f;

    for (int kvt = 0; kvt < NKV; kvt++) {
        __syncthreads();   // prev-iter K/VT reads done

        // ---- load K [kv][d] fp16 ----
        {
            const float* kg = k + base + kvt * BN * HD;
            #pragma unroll
            for (int i = 0; i < 4; i++) {
                int fi = tid + i * THREADS;      // 1024 float4s
                int n = fi >> 4, c4 = fi & 15;
                float4 val = *reinterpret_cast<const float4*>(kg + n * HD + c4 * 4);
                uint2 o;
                o.x = f2h2(val.x, val.y);
                o.y = f2h2(val.z, val.w);
                *reinterpret_cast<uint2*>(&sK[n * WSTR + c4 * 2]) = o;
            }
        }
        // ---- load V transposed -> VT[d][kv] fp16 ----
        // warp-pass (wid, p): d = wid*8 + (lane&7), chunk c = p*4 + (lane>>3), kv0 = 4c.
        // STS.64 banks 4(l&7)+2(l>>3)+8p: distinct per 16-lane phase -> conflict-free.
        {
            const float* vg = v + base + kvt * BN * HD;
            int d = wid * 8 + (lane & 7);
            #pragma unroll
            for (int p = 0; p < 4; p++) {
                int c = p * 4 + (lane >> 3);
                int kv0 = c * 4;
                float v0 = vg[(kv0 + 0) * HD + d];
                float v1 = vg[(kv0 + 1) * HD + d];
                float v2 = vg[(kv0 + 2) * HD + d];
                float v3 = vg[(kv0 + 3) * HD + d];
                uint2 o;
                o.x = f2h2(v0, v1);
                o.y = f2h2(v2, v3);
                *reinterpret_cast<uint2*>(&sVT[d * WSTR + c * 2]) = o;
            }
        }
        __syncthreads();

        // ---- GEMM1: S = Q @ K^T : 8 nt x 4 kt mmas ----
        float sacc[8][4];
        #pragma unroll
        for (int i = 0; i < 8; i++) {
            sacc[i][0] = 0.f; sacc[i][1] = 0.f; sacc[i][2] = 0.f; sacc[i][3] = 0.f;
        }
        #pragma unroll
        for (int nt = 0; nt < 8; nt++) {
            #pragma unroll
            for (int kt = 0; kt < 4; kt++) {
                const uint32_t* kp = &sK[(nt * 8 + g) * WSTR + kt * 8 + t];
                uint32_t bf[2] = { kp[0], kp[4] };
                mma_f16(sacc[nt], qf[kt], bf);
            }
        }

        // ---- online softmax (rows g and g+8) ----
        float tmax0 = -1e30f, tmax1 = -1e30f;
        #pragma unroll
        for (int nt = 0; nt < 8; nt++) {
            tmax0 = fmaxf(tmax0, fmaxf(sacc[nt][0], sacc[nt][1]));
            tmax1 = fmaxf(tmax1, fmaxf(sacc[nt][2], sacc[nt][3]));
        }
        tmax0 = fmaxf(tmax0, __shfl_xor_sync(0xffffffffu, tmax0, 1));
        tmax0 = fmaxf(tmax0, __shfl_xor_sync(0xffffffffu, tmax0, 2));
        tmax1 = fmaxf(tmax1, __shfl_xor_sync(0xffffffffu, tmax1, 1));
        tmax1 = fmaxf(tmax1, __shfl_xor_sync(0xffffffffu, tmax1, 2));

        float mn0 = fmaxf(mrow0, tmax0);
        float mn1 = fmaxf(mrow1, tmax1);
        float corr0 = __expf(mrow0 - mn0);
        float corr1 = __expf(mrow1 - mn1);
        mrow0 = mn0; mrow1 = mn1;

        float ts0 = 0.f, ts1 = 0.f;
        #pragma unroll
        for (int nt = 0; nt < 8; nt++) {
            float p00 = __expf(sacc[nt][0] - mn0);
            float p01 = __expf(sacc[nt][1] - mn0);
            float p10 = __expf(sacc[nt][2] - mn1);
            float p11 = __expf(sacc[nt][3] - mn1);
            ts0 += p00 + p01;
            ts1 += p10 + p11;
            // P[m][kv] fp16: cols nt*8+2t,2t+1 -> word nt*4+t
            sQ[(m0 + g)     * WSTR + nt * 4 + t] = f2h2(p00, p01);
            sQ[(m0 + g + 8) * WSTR + nt * 4 + t] = f2h2(p10, p11);
        }
        ts0 += __shfl_xor_sync(0xffffffffu, ts0, 1);
        ts0 += __shfl_xor_sync(0xffffffffu, ts0, 2);
        ts1 += __shfl_xor_sync(0xffffffffu, ts1, 1);
        ts1 += __shfl_xor_sync(0xffffffffu, ts1, 2);
        lrow0 = lrow0 * corr0 + ts0;
        lrow1 = lrow1 * corr1 + ts1;

        #pragma unroll
        for (int dt = 0; dt < 8; dt++) {
            oacc[dt][0] *= corr0; oacc[dt][1] *= corr0;
            oacc[dt][2] *= corr1; oacc[dt][3] *= corr1;
        }

        __syncwarp();   // own P rows visible across lanes

        // ---- GEMM2: O += P @ V : A-frags from P, B-frags from VT ----
        #pragma unroll
        for (int kt = 0; kt < 4; kt++) {
            const uint32_t* pp = &sQ[(m0 + g) * WSTR + kt * 8 + t];
            uint32_t af[4] = { pp[0], pp[8 * WSTR], pp[4], pp[8 * WSTR + 4] };
            #pragma unroll
            for (int dt = 0; dt < 8; dt++) {
                const uint32_t* vp = &sVT[(dt * 8 + g) * WSTR + kt * 8 + t];
                uint32_t bf[2] = { vp[0], vp[4] };
                mma_f16(oacc[dt], af, bf);
            }
        }
    }

    // ---- epilogue: O /= l, store ----
    float inv0 = 1.f / lrow0;
    float inv1 = 1.f / lrow1;
    float* og = out + base + qt * BM * HD;
    #pragma unroll
    for (int dt = 0; dt < 8; dt++) {
        int c = dt * 8 + 2 * t;
        float2 v0 = make_float2(oacc[dt][0] * inv0, oacc[dt][1] * inv0);
        float2 v1 = make_float2(oacc[dt][2] * inv1, oacc[dt][3] * inv1);
        *reinterpret_cast<float2*>(og + (m0 + g) * HD + c) = v0;
        *reinterpret_cast<float2*>(og + (m0 + g + 8) * HD + c) = v1;
    }
}

}  // namespace

extern "C" void kernel_launch(void* const* d_in, const int* in_sizes, int n_in,
                              void* d_out, int out_size) {
    const float* q = (const float*)d_in[0];
    const float* k = (const float*)d_in[1];
    const float* v = (const float*)d_in[2];
    float* out = (float*)d_out;

    const size_t smem_bytes = SMEM_WORDS * sizeof(uint32_t);  // 36864 B
    cudaFuncSetAttribute(fa_f16_kernel,
                         cudaFuncAttributeMaxDynamicSharedMemorySize, (int)smem_bytes);

    dim3 grid(SEQ / BM, 64);
    fa_f16_kernel<<<grid, THREADS, smem_bytes>>>(q, k, v, out);
}

// round 6
// speedup vs baseline: 2.5334x; 1.0908x over previous
#include <cuda_runtime.h>
#include <cuda_fp16.h>
#include <cstdint>

// Flash attention, fp16 m16n8k16 mma.sync, round 6 (= round 5 re-bench after
// infra "device busy" failure; source unchanged by design):
// ldmatrix fragments (x4 / x4.trans), V untransposed + LDSM.T,
// double-buffered K/V tiles, single __syncthreads per kv iteration.

namespace {

constexpr int SEQ = 2048, HD = 64, BM = 128, BN = 64, THREADS = 256;
constexpr int NKV = SEQ / BN;

constexpr int WSTR = 36;                 // 64 f16 = 32 words + 4 pad (stride 4 mod 32)
constexpr int KV_WORDS = BN * WSTR;      // 2304 words per tile buffer
constexpr int SK_OFF = BM * WSTR;        // Q/P region: 4608 words
constexpr int SV_OFF = SK_OFF + 2 * KV_WORDS;
constexpr int SMEM_WORDS = SV_OFF + 2 * KV_WORDS;   // 13824 w = 55296 B

__device__ __forceinline__ uint32_t f2h2(float lo, float hi) {
    uint32_t r;
    asm("cvt.rn.f16x2.f32 %0, %1, %2;" : "=r"(r) : "f"(hi), "f"(lo));
    return r;
}
__device__ __forceinline__ uint32_t smem_u32(const void* p) {
    uint32_t a;
    asm("{ .reg .u64 t; cvta.to.shared.u64 t, %1; cvt.u32.u64 %0, t; }" : "=r"(a) : "l"(p));
    return a;
}
__device__ __forceinline__ void mma_f16(float c[4], const uint32_t a[4], const uint32_t b0,
                                        const uint32_t b1) {
    asm volatile(
        "mma.sync.aligned.m16n8k16.row.col.f32.f16.f16.f32 "
        "{%0,%1,%2,%3}, {%4,%5,%6,%7}, {%8,%9}, {%0,%1,%2,%3};\n"
        : "+f"(c[0]), "+f"(c[1]), "+f"(c[2]), "+f"(c[3])
        : "r"(a[0]), "r"(a[1]), "r"(a[2]), "r"(a[3]), "r"(b0), "r"(b1));
}
__device__ __forceinline__ void ldsm4(uint32_t& r0, uint32_t& r1, uint32_t& r2, uint32_t& r3,
                                      uint32_t a) {
    asm volatile("ldmatrix.sync.aligned.m8n8.x4.shared.b16 {%0,%1,%2,%3}, [%4];"
                 : "=r"(r0), "=r"(r1), "=r"(r2), "=r"(r3) : "r"(a));
}
__device__ __forceinline__ void ldsm4t(uint32_t& r0, uint32_t& r1, uint32_t& r2, uint32_t& r3,
                                       uint32_t a) {
    asm volatile("ldmatrix.sync.aligned.m8n8.x4.trans.shared.b16 {%0,%1,%2,%3}, [%4];"
                 : "=r"(r0), "=r"(r1), "=r"(r2), "=r"(r3) : "r"(a));
}

__global__ void __launch_bounds__(THREADS, 2)
fa_f16_kernel(const float* __restrict__ q, const float* __restrict__ k,
              const float* __restrict__ v, float* __restrict__ out)
{
    extern __shared__ uint32_t smem[];
    const uint32_t sb = smem_u32(smem);
    const uint32_t sQb = sb;                       // Q/P bytes
    const uint32_t sKb = sb + SK_OFF * 4;
    const uint32_t sVb = sb + SV_OFF * 4;

    const int bh   = blockIdx.y;
    const int qt   = blockIdx.x;
    const int tid  = threadIdx.x;
    const int wid  = tid >> 5;
    const int lane = tid & 31;
    const int g    = lane >> 2;
    const int t    = lane & 3;
    const int base = bh * SEQ * HD;
    const int m0   = wid * 16;

    // ldmatrix per-lane word offsets within a 16x16 tile
    // A-type (and V-trans): row split on bit3, col-half on bit4
    const int a_off_w = ((lane & 7) + ((lane >> 3) & 1) * 8) * WSTR + ((lane >> 4) & 1) * 4;
    // B-type (K): row split on bit4, k-half on bit3
    const int b_off_w = ((lane & 7) + ((lane >> 4) & 1) * 8) * WSTR + ((lane >> 3) & 1) * 4;

    const float* kg = k + base;
    const float* vg = v + base;

    // ---- prologue: Q (scaled) + KV tile 0 ----
    {
        const float* qg = q + base + qt * BM * HD;
        #pragma unroll
        for (int i = 0; i < 8; i++) {
            int fi = tid + i * THREADS;
            int m = fi >> 4, c4 = fi & 15;
            float4 val = *reinterpret_cast<const float4*>(qg + m * HD + c4 * 4);
            uint2 o;
            o.x = f2h2(val.x * 0.125f, val.y * 0.125f);
            o.y = f2h2(val.z * 0.125f, val.w * 0.125f);
            *reinterpret_cast<uint2*>(&smem[m * WSTR + c4 * 2]) = o;
        }
        #pragma unroll
        for (int i = 0; i < 4; i++) {
            int fi = tid + i * THREADS;
            int n = fi >> 4, c4 = fi & 15;
            float4 kv4 = *reinterpret_cast<const float4*>(kg + n * HD + c4 * 4);
            uint2 ok; ok.x = f2h2(kv4.x, kv4.y); ok.y = f2h2(kv4.z, kv4.w);
            *reinterpret_cast<uint2*>(&smem[SK_OFF + n * WSTR + c4 * 2]) = ok;
            float4 vv4 = *reinterpret_cast<const float4*>(vg + n * HD + c4 * 4);
            uint2 ov; ov.x = f2h2(vv4.x, vv4.y); ov.y = f2h2(vv4.z, vv4.w);
            *reinterpret_cast<uint2*>(&smem[SV_OFF + n * WSTR + c4 * 2]) = ov;
        }
    }
    __syncthreads();

    // ---- hoist Q fragments via ldmatrix ----
    uint32_t qf[4][4];
    #pragma unroll
    for (int kt = 0; kt < 4; kt++)
        ldsm4(qf[kt][0], qf[kt][1], qf[kt][2], qf[kt][3],
              sQb + 4u * (m0 * WSTR + kt * 8 + a_off_w));

    float oacc[8][4];
    #pragma unroll
    for (int i = 0; i < 8; i++)
        #pragma unroll
        for (int j = 0; j < 4; j++) oacc[i][j] = 0.f;

    float mrow0 = -1e30f, mrow1 = -1e30f;
    float lrow0 = 0.f, lrow1 = 0.f;

    // per-thread tile-load indices
    const int ln = tid >> 4;           // row pair base (0..15), rows ln + 16i
    const int lc = (tid & 15) * 2;     // word col

    for (int kvt = 0; kvt < NKV; kvt++) {
        const uint32_t curK = sKb + (uint32_t)((kvt & 1) * KV_WORDS * 4);
        const uint32_t curV = sVb + (uint32_t)((kvt & 1) * KV_WORDS * 4);
        const int nxt = (kvt & 1) ^ 1;
        const bool has_next = (kvt + 1) < NKV;

        // prefetch next K tile (regs)
        float4 kpre[4];
        if (has_next) {
            const float* kgn = kg + (kvt + 1) * BN * HD;
            #pragma unroll
            for (int i = 0; i < 4; i++)
                kpre[i] = *reinterpret_cast<const float4*>(kgn + (ln + i * 16) * HD + lc * 2);
        }

        // ---- GEMM1: S = Q @ K^T ----
        float sacc[8][4];
        #pragma unroll
        for (int i = 0; i < 8; i++) {
            sacc[i][0] = 0.f; sacc[i][1] = 0.f; sacc[i][2] = 0.f; sacc[i][3] = 0.f;
        }
        #pragma unroll
        for (int kt = 0; kt < 4; kt++) {
            #pragma unroll
            for (int ntp = 0; ntp < 4; ntp++) {
                uint32_t r0, r1, r2, r3;
                ldsm4(r0, r1, r2, r3, curK + 4u * (ntp * 16 * WSTR + kt * 8 + b_off_w));
                mma_f16(sacc[2 * ntp],     qf[kt], r0, r1);
                mma_f16(sacc[2 * ntp + 1], qf[kt], r2, r3);
            }
        }

        // store prefetched K, then prefetch next V
        float4 vpre[4];
        if (has_next) {
            uint32_t* sKn = smem + SK_OFF + nxt * KV_WORDS;
            #pragma unroll
            for (int i = 0; i < 4; i++) {
                uint2 o;
                o.x = f2h2(kpre[i].x, kpre[i].y);
                o.y = f2h2(kpre[i].z, kpre[i].w);
                *reinterpret_cast<uint2*>(&sKn[(ln + i * 16) * WSTR + lc]) = o;
            }
            const float* vgn = vg + (kvt + 1) * BN * HD;
            #pragma unroll
            for (int i = 0; i < 4; i++)
                vpre[i] = *reinterpret_cast<const float4*>(vgn + (ln + i * 16) * HD + lc * 2);
        }

        // ---- online softmax ----
        float tmax0 = -1e30f, tmax1 = -1e30f;
        #pragma unroll
        for (int nt = 0; nt < 8; nt++) {
            tmax0 = fmaxf(tmax0, fmaxf(sacc[nt][0], sacc[nt][1]));
            tmax1 = fmaxf(tmax1, fmaxf(sacc[nt][2], sacc[nt][3]));
        }
        tmax0 = fmaxf(tmax0, __shfl_xor_sync(0xffffffffu, tmax0, 1));
        tmax0 = fmaxf(tmax0, __shfl_xor_sync(0xffffffffu, tmax0, 2));
        tmax1 = fmaxf(tmax1, __shfl_xor_sync(0xffffffffu, tmax1, 1));
        tmax1 = fmaxf(tmax1, __shfl_xor_sync(0xffffffffu, tmax1, 2));

        float mn0 = fmaxf(mrow0, tmax0);
        float mn1 = fmaxf(mrow1, tmax1);
        float corr0 = __expf(mrow0 - mn0);
        float corr1 = __expf(mrow1 - mn1);
        mrow0 = mn0; mrow1 = mn1;

        float ts0 = 0.f, ts1 = 0.f;
        #pragma unroll
        for (int nt = 0; nt < 8; nt++) {
            float p00 = __expf(sacc[nt][0] - mn0);
            float p01 = __expf(sacc[nt][1] - mn0);
            float p10 = __expf(sacc[nt][2] - mn1);
            float p11 = __expf(sacc[nt][3] - mn1);
            ts0 += p00 + p01;
            ts1 += p10 + p11;
            smem[(m0 + g)     * WSTR + nt * 4 + t] = f2h2(p00, p01);
            smem[(m0 + g + 8) * WSTR + nt * 4 + t] = f2h2(p10, p11);
        }
        ts0 += __shfl_xor_sync(0xffffffffu, ts0, 1);
        ts0 += __shfl_xor_sync(0xffffffffu, ts0, 2);
        ts1 += __shfl_xor_sync(0xffffffffu, ts1, 1);
        ts1 += __shfl_xor_sync(0xffffffffu, ts1, 2);
        lrow0 = lrow0 * corr0 + ts0;
        lrow1 = lrow1 * corr1 + ts1;

        #pragma unroll
        for (int dt = 0; dt < 8; dt++) {
            oacc[dt][0] *= corr0; oacc[dt][1] *= corr0;
            oacc[dt][2] *= corr1; oacc[dt][3] *= corr1;
        }

        // store prefetched V tile
        if (has_next) {
            uint32_t* sVn = smem + SV_OFF + nxt * KV_WORDS;
            #pragma unroll
            for (int i = 0; i < 4; i++) {
                uint2 o;
                o.x = f2h2(vpre[i].x, vpre[i].y);
                o.y = f2h2(vpre[i].z, vpre[i].w);
                *reinterpret_cast<uint2*>(&sVn[(ln + i * 16) * WSTR + lc]) = o;
            }
        }

        __syncwarp();   // own P rows visible across lanes

        // ---- GEMM2: O += P @ V (V[kv][d] via ldmatrix.trans) ----
        #pragma unroll
        for (int kt = 0; kt < 4; kt++) {
            uint32_t af[4];
            ldsm4(af[0], af[1], af[2], af[3],
                  sQb + 4u * (m0 * WSTR + kt * 8 + a_off_w));
            #pragma unroll
            for (int dtp = 0; dtp < 4; dtp++) {
                uint32_t r0, r1, r2, r3;
                ldsm4t(r0, r1, r2, r3, curV + 4u * (kt * 16 * WSTR + dtp * 8 + a_off_w));
                mma_f16(oacc[2 * dtp],     af, r0, r1);
                mma_f16(oacc[2 * dtp + 1], af, r2, r3);
            }
        }

        __syncthreads();
    }

    // ---- epilogue ----
    float inv0 = 1.f / lrow0;
    float inv1 = 1.f / lrow1;
    float* og = out + base + qt * BM * HD;
    #pragma unroll
    for (int dt = 0; dt < 8; dt++) {
        int c = dt * 8 + 2 * t;
        float2 v0 = make_float2(oacc[dt][0] * inv0, oacc[dt][1] * inv0);
        float2 v1 = make_float2(oacc[dt][2] * inv1, oacc[dt][3] * inv1);
        *reinterpret_cast<float2*>(og + (m0 + g) * HD + c) = v0;
        *reinterpret_cast<float2*>(og + (m0 + g + 8) * HD + c) = v1;
    }
}

}  // namespace

extern "C" void kernel_launch(void* const* d_in, const int* in_sizes, int n_in,
                              void* d_out, int out_size) {
    const float* q = (const float*)d_in[0];
    const float* k = (const float*)d_in[1];
    const float* v = (const float*)d_in[2];
    float* out = (float*)d_out;

    const size_t smem_bytes = SMEM_WORDS * sizeof(uint32_t);  // 55296 B
    cudaFuncSetAttribute(fa_f16_kernel,
                         cudaFuncAttributeMaxDynamicSharedMemorySize, (int)smem_bytes);

    dim3 grid(SEQ / BM, 64);
    fa_f16_kernel<<<grid, THREADS, smem_bytes>>>(q, k, v, out);
}

// round 7
// speedup vs baseline: 2.8478x; 1.1241x over previous
#include <cuda_runtime.h>
#include <cuda_fp16.h>
#include <cstdint>

// Flash attention, fp16 m16n8k16 mma.sync, round 7:
// P kept entirely in registers (C-frag layout == A-frag layout for fp16 k16),
// no P smem round-trip, softmax in exp2 domain, double-buffered K/V, ldmatrix.

namespace {

constexpr int SEQ = 2048, HD = 64, BM = 128, BN = 64, THREADS = 256;
constexpr int NKV = SEQ / BN;

constexpr int WSTR = 36;                 // 64 f16 = 32 words + 4 pad
constexpr int KV_WORDS = BN * WSTR;
constexpr int SK_OFF = BM * WSTR;        // Q region (prologue only)
constexpr int SV_OFF = SK_OFF + 2 * KV_WORDS;
constexpr int SMEM_WORDS = SV_OFF + 2 * KV_WORDS;   // 55296 B

__device__ __forceinline__ uint32_t f2h2(float lo, float hi) {
    uint32_t r;
    asm("cvt.rn.f16x2.f32 %0, %1, %2;" : "=r"(r) : "f"(hi), "f"(lo));
    return r;
}
__device__ __forceinline__ float ex2(float x) {
    float r; asm("ex2.approx.ftz.f32 %0, %1;" : "=f"(r) : "f"(x)); return r;
}
__device__ __forceinline__ uint32_t smem_u32(const void* p) {
    uint32_t a;
    asm("{ .reg .u64 t; cvta.to.shared.u64 t, %1; cvt.u32.u64 %0, t; }" : "=r"(a) : "l"(p));
    return a;
}
__device__ __forceinline__ void mma_f16(float c[4], const uint32_t a[4], const uint32_t b0,
                                        const uint32_t b1) {
    asm volatile(
        "mma.sync.aligned.m16n8k16.row.col.f32.f16.f16.f32 "
        "{%0,%1,%2,%3}, {%4,%5,%6,%7}, {%8,%9}, {%0,%1,%2,%3};\n"
        : "+f"(c[0]), "+f"(c[1]), "+f"(c[2]), "+f"(c[3])
        : "r"(a[0]), "r"(a[1]), "r"(a[2]), "r"(a[3]), "r"(b0), "r"(b1));
}
__device__ __forceinline__ void ldsm4(uint32_t& r0, uint32_t& r1, uint32_t& r2, uint32_t& r3,
                                      uint32_t a) {
    asm volatile("ldmatrix.sync.aligned.m8n8.x4.shared.b16 {%0,%1,%2,%3}, [%4];"
                 : "=r"(r0), "=r"(r1), "=r"(r2), "=r"(r3) : "r"(a));
}
__device__ __forceinline__ void ldsm4t(uint32_t& r0, uint32_t& r1, uint32_t& r2, uint32_t& r3,
                                       uint32_t a) {
    asm volatile("ldmatrix.sync.aligned.m8n8.x4.trans.shared.b16 {%0,%1,%2,%3}, [%4];"
                 : "=r"(r0), "=r"(r1), "=r"(r2), "=r"(r3) : "r"(a));
}

__global__ void __launch_bounds__(THREADS, 2)
fa_f16_kernel(const float* __restrict__ q, const float* __restrict__ k,
              const float* __restrict__ v, float* __restrict__ out)
{
    extern __shared__ uint32_t smem[];
    const uint32_t sb = smem_u32(smem);
    const uint32_t sQb = sb;
    const uint32_t sKb = sb + SK_OFF * 4;
    const uint32_t sVb = sb + SV_OFF * 4;

    const int bh   = blockIdx.y;
    const int qt   = blockIdx.x;
    const int tid  = threadIdx.x;
    const int wid  = tid >> 5;
    const int lane = tid & 31;
    const int base = bh * SEQ * HD;
    const int m0   = wid * 16;

    // Q scale: 1/sqrt(64) * log2(e)  (softmax runs in base-2 domain)
    const float QSCALE = 0.125f * 1.4426950408889634f;

    const int a_off_w = ((lane & 7) + ((lane >> 3) & 1) * 8) * WSTR + ((lane >> 4) & 1) * 4;
    const int b_off_w = ((lane & 7) + ((lane >> 4) & 1) * 8) * WSTR + ((lane >> 3) & 1) * 4;

    const float* kg = k + base;
    const float* vg = v + base;

    // ---- prologue: Q (scaled) + KV tile 0 ----
    {
        const float* qg = q + base + qt * BM * HD;
        #pragma unroll
        for (int i = 0; i < 8; i++) {
            int fi = tid + i * THREADS;
            int m = fi >> 4, c4 = fi & 15;
            float4 val = *reinterpret_cast<const float4*>(qg + m * HD + c4 * 4);
            uint2 o;
            o.x = f2h2(val.x * QSCALE, val.y * QSCALE);
            o.y = f2h2(val.z * QSCALE, val.w * QSCALE);
            *reinterpret_cast<uint2*>(&smem[m * WSTR + c4 * 2]) = o;
        }
        #pragma unroll
        for (int i = 0; i < 4; i++) {
            int fi = tid + i * THREADS;
            int n = fi >> 4, c4 = fi & 15;
            float4 kv4 = *reinterpret_cast<const float4*>(kg + n * HD + c4 * 4);
            uint2 ok; ok.x = f2h2(kv4.x, kv4.y); ok.y = f2h2(kv4.z, kv4.w);
            *reinterpret_cast<uint2*>(&smem[SK_OFF + n * WSTR + c4 * 2]) = ok;
            float4 vv4 = *reinterpret_cast<const float4*>(vg + n * HD + c4 * 4);
            uint2 ov; ov.x = f2h2(vv4.x, vv4.y); ov.y = f2h2(vv4.z, vv4.w);
            *reinterpret_cast<uint2*>(&smem[SV_OFF + n * WSTR + c4 * 2]) = ov;
        }
    }
    __syncthreads();

    // ---- hoist Q fragments ----
    uint32_t qf[4][4];
    #pragma unroll
    for (int kt = 0; kt < 4; kt++)
        ldsm4(qf[kt][0], qf[kt][1], qf[kt][2], qf[kt][3],
              sQb + 4u * (m0 * WSTR + kt * 8 + a_off_w));

    float oacc[8][4];
    #pragma unroll
    for (int i = 0; i < 8; i++)
        #pragma unroll
        for (int j = 0; j < 4; j++) oacc[i][j] = 0.f;

    float mrow0 = -1e30f, mrow1 = -1e30f;   // log2-domain running max
    float lrow0 = 0.f, lrow1 = 0.f;

    const int ln = tid >> 4;
    const int lc = (tid & 15) * 2;

    for (int kvt = 0; kvt < NKV; kvt++) {
        const uint32_t curK = sKb + (uint32_t)((kvt & 1) * KV_WORDS * 4);
        const uint32_t curV = sVb + (uint32_t)((kvt & 1) * KV_WORDS * 4);
        const int nxt = (kvt & 1) ^ 1;
        const bool has_next = (kvt + 1) < NKV;

        // prefetch next K tile into regs (covered by GEMM1)
        float4 kpre[4];
        if (has_next) {
            const float* kgn = kg + (kvt + 1) * BN * HD;
            #pragma unroll
            for (int i = 0; i < 4; i++)
                kpre[i] = *reinterpret_cast<const float4*>(kgn + (ln + i * 16) * HD + lc * 2);
        }

        // ---- GEMM1: S = Q @ K^T (log2-scaled) ----
        float sacc[8][4];
        #pragma unroll
        for (int i = 0; i < 8; i++) {
            sacc[i][0] = 0.f; sacc[i][1] = 0.f; sacc[i][2] = 0.f; sacc[i][3] = 0.f;
        }
        #pragma unroll
        for (int kt = 0; kt < 4; kt++) {
            #pragma unroll
            for (int ntp = 0; ntp < 4; ntp++) {
                uint32_t r0, r1, r2, r3;
                ldsm4(r0, r1, r2, r3, curK + 4u * (ntp * 16 * WSTR + kt * 8 + b_off_w));
                mma_f16(sacc[2 * ntp],     qf[kt], r0, r1);
                mma_f16(sacc[2 * ntp + 1], qf[kt], r2, r3);
            }
        }

        // store prefetched K, prefetch next V (covered by softmax + GEMM2)
        float4 vpre[4];
        if (has_next) {
            uint32_t* sKn = smem + SK_OFF + nxt * KV_WORDS;
            #pragma unroll
            for (int i = 0; i < 4; i++) {
                uint2 o;
                o.x = f2h2(kpre[i].x, kpre[i].y);
                o.y = f2h2(kpre[i].z, kpre[i].w);
                *reinterpret_cast<uint2*>(&sKn[(ln + i * 16) * WSTR + lc]) = o;
            }
            const float* vgn = vg + (kvt + 1) * BN * HD;
            #pragma unroll
            for (int i = 0; i < 4; i++)
                vpre[i] = *reinterpret_cast<const float4*>(vgn + (ln + i * 16) * HD + lc * 2);
        }

        // ---- online softmax (base-2), P packed into registers ----
        float tmax0 = -1e30f, tmax1 = -1e30f;
        #pragma unroll
        for (int nt = 0; nt < 8; nt++) {
            tmax0 = fmaxf(tmax0, fmaxf(sacc[nt][0], sacc[nt][1]));
            tmax1 = fmaxf(tmax1, fmaxf(sacc[nt][2], sacc[nt][3]));
        }
        tmax0 = fmaxf(tmax0, __shfl_xor_sync(0xffffffffu, tmax0, 1));
        tmax0 = fmaxf(tmax0, __shfl_xor_sync(0xffffffffu, tmax0, 2));
        tmax1 = fmaxf(tmax1, __shfl_xor_sync(0xffffffffu, tmax1, 1));
        tmax1 = fmaxf(tmax1, __shfl_xor_sync(0xffffffffu, tmax1, 2));

        float mn0 = fmaxf(mrow0, tmax0);
        float mn1 = fmaxf(mrow1, tmax1);
        float corr0 = ex2(mrow0 - mn0);
        float corr1 = ex2(mrow1 - mn1);
        mrow0 = mn0; mrow1 = mn1;

        uint32_t p2[8][2];   // packed P fragments: [nt][row-half]
        float ts0 = 0.f, ts1 = 0.f;
        #pragma unroll
        for (int nt = 0; nt < 8; nt++) {
            float p00 = ex2(sacc[nt][0] - mn0);
            float p01 = ex2(sacc[nt][1] - mn0);
            float p10 = ex2(sacc[nt][2] - mn1);
            float p11 = ex2(sacc[nt][3] - mn1);
            ts0 += p00 + p01;
            ts1 += p10 + p11;
            p2[nt][0] = f2h2(p00, p01);
            p2[nt][1] = f2h2(p10, p11);
        }
        ts0 += __shfl_xor_sync(0xffffffffu, ts0, 1);
        ts0 += __shfl_xor_sync(0xffffffffu, ts0, 2);
        ts1 += __shfl_xor_sync(0xffffffffu, ts1, 1);
        ts1 += __shfl_xor_sync(0xffffffffu, ts1, 2);
        lrow0 = lrow0 * corr0 + ts0;
        lrow1 = lrow1 * corr1 + ts1;

        #pragma unroll
        for (int dt = 0; dt < 8; dt++) {
            oacc[dt][0] *= corr0; oacc[dt][1] *= corr0;
            oacc[dt][2] *= corr1; oacc[dt][3] *= corr1;
        }

        // ---- GEMM2: O += P @ V  (A-frags straight from registers) ----
        #pragma unroll
        for (int kt = 0; kt < 4; kt++) {
            uint32_t af[4] = { p2[2 * kt][0], p2[2 * kt][1],
                               p2[2 * kt + 1][0], p2[2 * kt + 1][1] };
            #pragma unroll
            for (int dtp = 0; dtp < 4; dtp++) {
                uint32_t r0, r1, r2, r3;
                ldsm4t(r0, r1, r2, r3, curV + 4u * (kt * 16 * WSTR + dtp * 8 + a_off_w));
                mma_f16(oacc[2 * dtp],     af, r0, r1);
                mma_f16(oacc[2 * dtp + 1], af, r2, r3);
            }
        }

        // store prefetched V tile
        if (has_next) {
            uint32_t* sVn = smem + SV_OFF + nxt * KV_WORDS;
            #pragma unroll
            for (int i = 0; i < 4; i++) {
                uint2 o;
                o.x = f2h2(vpre[i].x, vpre[i].y);
                o.y = f2h2(vpre[i].z, vpre[i].w);
                *reinterpret_cast<uint2*>(&sVn[(ln + i * 16) * WSTR + lc]) = o;
            }
        }

        __syncthreads();
    }

    // ---- epilogue ----
    float inv0 = 1.f / lrow0;
    float inv1 = 1.f / lrow1;
    const int g = lane >> 2, t = lane & 3;
    float* og = out + base + qt * BM * HD;
    #pragma unroll
    for (int dt = 0; dt < 8; dt++) {
        int c = dt * 8 + 2 * t;
        float2 v0 = make_float2(oacc[dt][0] * inv0, oacc[dt][1] * inv0);
        float2 v1 = make_float2(oacc[dt][2] * inv1, oacc[dt][3] * inv1);
        *reinterpret_cast<float2*>(og + (m0 + g) * HD + c) = v0;
        *reinterpret_cast<float2*>(og + (m0 + g + 8) * HD + c) = v1;
    }
}

}  // namespace

extern "C" void kernel_launch(void* const* d_in, const int* in_sizes, int n_in,
                              void* d_out, int out_size) {
    const float* q = (const float*)d_in[0];
    const float* k = (const float*)d_in[1];
    const float* v = (const float*)d_in[2];
    float* out = (float*)d_out;

    const size_t smem_bytes = SMEM_WORDS * sizeof(uint32_t);  // 55296 B
    cudaFuncSetAttribute(fa_f16_kernel,
                         cudaFuncAttributeMaxDynamicSharedMemorySize, (int)smem_bytes);

    dim3 grid(SEQ / BM, 64);
    fa_f16_kernel<<<grid, THREADS, smem_bytes>>>(q, k, v, out);
}